// round 4
// baseline (speedup 1.0000x reference)
#include <cuda_runtime.h>

#define D     128
#define LSEQ  4096
#define NB    4
#define BQ    64
#define BK    64
#define NTH   256
#define KSTR  132   // smem row stride (floats), padded to limit bank conflicts
#define PSTR  65    // smem stride for P tile

// Scratch for projected Q, K, V (8 MB each) — __device__ globals per alloc rules.
__device__ float g_q[NB * LSEQ * D];
__device__ float g_k[NB * LSEQ * D];
__device__ float g_v[NB * LSEQ * D];

// ---------------------------------------------------------------------------
// Fused QKV projection: y = x @ W^T + b.  blockIdx.z selects (x,W,b,out).
// Block computes a 64-row x 128-col output tile. 256 threads, 4x8 regs each.
// ---------------------------------------------------------------------------
__global__ __launch_bounds__(NTH) void proj_kernel(
    const float* __restrict__ x1, const float* __restrict__ x2, const float* __restrict__ x3,
    const float* __restrict__ Wq, const float* __restrict__ bq,
    const float* __restrict__ Wk, const float* __restrict__ bk,
    const float* __restrict__ Wv, const float* __restrict__ bv)
{
    extern __shared__ float sm[];
    float* xs = sm;             // BQ x KSTR
    float* ws = sm + BQ * KSTR; // D  x KSTR

    const int z = blockIdx.z;
    const float* x    = (z == 0) ? x1 : (z == 1) ? x2 : x3;
    const float* W    = (z == 0) ? Wq : (z == 1) ? Wk : Wv;
    const float* bias = (z == 0) ? bq : (z == 1) ? bk : bv;
    float*       y    = (z == 0) ? g_q : (z == 1) ? g_k : g_v;

    const int row0 = blockIdx.x * BQ;
    const int tid  = threadIdx.x;

    // Load x tile (64x128) into smem, float4 coalesced.
    #pragma unroll
    for (int c = 0; c < (BQ * D) / (NTH * 4); ++c) {
        int li  = c * NTH * 4 + tid * 4;
        int r   = li >> 7;
        int col = li & (D - 1);
        float4 val = *reinterpret_cast<const float4*>(x + (row0 + r) * D + col);
        *reinterpret_cast<float4*>(xs + r * KSTR + col) = val;
    }
    // Load full W (128x128) into smem.
    #pragma unroll
    for (int c = 0; c < (D * D) / (NTH * 4); ++c) {
        int li  = c * NTH * 4 + tid * 4;
        int r   = li >> 7;
        int col = li & (D - 1);
        float4 val = *reinterpret_cast<const float4*>(W + li);
        *reinterpret_cast<float4*>(ws + r * KSTR + col) = val;
    }
    __syncthreads();

    const int tx = tid & 15;   // 16 threads across output cols
    const int ty = tid >> 4;   // 16 thread-groups across rows

    float acc[4][8];
    #pragma unroll
    for (int i = 0; i < 4; ++i)
        #pragma unroll
        for (int j = 0; j < 8; ++j) acc[i][j] = 0.f;

    for (int d = 0; d < D; d += 4) {
        float4 xv[4];
        #pragma unroll
        for (int i = 0; i < 4; ++i)
            xv[i] = *reinterpret_cast<const float4*>(xs + (4 * ty + i) * KSTR + d);
        #pragma unroll
        for (int j = 0; j < 8; ++j) {
            // col = tx + 16*j → consecutive rows across tx → <=2-way LDS conflict
            float4 wv = *reinterpret_cast<const float4*>(ws + (tx + 16 * j) * KSTR + d);
            #pragma unroll
            for (int i = 0; i < 4; ++i) {
                acc[i][j] += xv[i].x * wv.x;
                acc[i][j] += xv[i].y * wv.y;
                acc[i][j] += xv[i].z * wv.z;
                acc[i][j] += xv[i].w * wv.w;
            }
        }
    }

    #pragma unroll
    for (int j = 0; j < 8; ++j) {
        const int e  = tx + 16 * j;
        const float be = bias[e];
        #pragma unroll
        for (int i = 0; i < 4; ++i) {
            y[(row0 + 4 * ty + i) * D + e] = acc[i][j] + be;
        }
    }
}

// ---------------------------------------------------------------------------
// Flash attention, fp32. One CTA = 64 query rows of one batch.
// Online softmax over 64-wide KV tiles; K and V share one smem buffer.
// ---------------------------------------------------------------------------
__global__ __launch_bounds__(NTH) void attn_kernel(float* __restrict__ out)
{
    extern __shared__ float sm[];
    float* qs  = sm;                  // BQ x KSTR
    float* kvs = sm + BQ * KSTR;      // BK x KSTR (K then V, reused)
    float* ps  = kvs + BK * KSTR;     // BQ x PSTR

    const int b    = blockIdx.y;
    const int row0 = blockIdx.x * BQ;
    const float* q = g_q + b * LSEQ * D;
    const float* k = g_k + b * LSEQ * D;
    const float* v = g_v + b * LSEQ * D;

    const int tid = threadIdx.x;
    const int tx  = tid & 15;   // lane bits 0..3
    const int ty  = tid >> 4;

    const float scale = 0.08838834764831845f;  // 1/sqrt(128)

    // Load Q tile pre-scaled.
    #pragma unroll
    for (int c = 0; c < (BQ * D) / (NTH * 4); ++c) {
        int li  = c * NTH * 4 + tid * 4;
        int r   = li >> 7;
        int col = li & (D - 1);
        float4 val = *reinterpret_cast<const float4*>(q + (row0 + r) * D + col);
        val.x *= scale; val.y *= scale; val.z *= scale; val.w *= scale;
        *reinterpret_cast<float4*>(qs + r * KSTR + col) = val;
    }

    float m[4], l[4], o[4][8];
    #pragma unroll
    for (int i = 0; i < 4; ++i) {
        m[i] = -1e30f;
        l[i] = 0.f;
        #pragma unroll
        for (int j = 0; j < 8; ++j) o[i][j] = 0.f;
    }

    for (int kt = 0; kt < LSEQ / BK; ++kt) {
        __syncthreads();  // previous V-phase reads done before overwriting kvs

        // Load K tile.
        #pragma unroll
        for (int c = 0; c < (BK * D) / (NTH * 4); ++c) {
            int li  = c * NTH * 4 + tid * 4;
            int r   = li >> 7;
            int col = li & (D - 1);
            float4 val = *reinterpret_cast<const float4*>(k + (kt * BK + r) * D + col);
            *reinterpret_cast<float4*>(kvs + r * KSTR + col) = val;
        }
        __syncthreads();

        // S = Q K^T (scaled): thread owns rows 4*ty+i, cols tx+16*j.
        float acc[4][4];
        #pragma unroll
        for (int i = 0; i < 4; ++i)
            #pragma unroll
            for (int j = 0; j < 4; ++j) acc[i][j] = 0.f;

        for (int d = 0; d < D; d += 4) {
            float4 qv[4];
            #pragma unroll
            for (int i = 0; i < 4; ++i)
                qv[i] = *reinterpret_cast<const float4*>(qs + (4 * ty + i) * KSTR + d);
            #pragma unroll
            for (int j = 0; j < 4; ++j) {
                float4 kv4 = *reinterpret_cast<const float4*>(kvs + (tx + 16 * j) * KSTR + d);
                #pragma unroll
                for (int i = 0; i < 4; ++i) {
                    acc[i][j] += qv[i].x * kv4.x;
                    acc[i][j] += qv[i].y * kv4.y;
                    acc[i][j] += qv[i].z * kv4.z;
                    acc[i][j] += qv[i].w * kv4.w;
                }
            }
        }

        // Online softmax per row; row spread across the 16 tx lanes.
        #pragma unroll
        for (int i = 0; i < 4; ++i) {
            float mt = acc[i][0];
            mt = fmaxf(mt, acc[i][1]);
            mt = fmaxf(mt, acc[i][2]);
            mt = fmaxf(mt, acc[i][3]);
            #pragma unroll
            for (int off = 8; off >= 1; off >>= 1)
                mt = fmaxf(mt, __shfl_xor_sync(0xffffffffu, mt, off));

            float mn    = fmaxf(m[i], mt);
            float alpha = __expf(m[i] - mn);
            float rs    = 0.f;
            #pragma unroll
            for (int j = 0; j < 4; ++j) {
                float p = __expf(acc[i][j] - mn);
                acc[i][j] = p;
                rs += p;
            }
            #pragma unroll
            for (int off = 8; off >= 1; off >>= 1)
                rs += __shfl_xor_sync(0xffffffffu, rs, off);

            l[i] = l[i] * alpha + rs;
            m[i] = mn;
            #pragma unroll
            for (int j = 0; j < 8; ++j) o[i][j] *= alpha;
            #pragma unroll
            for (int j = 0; j < 4; ++j)
                ps[(4 * ty + i) * PSTR + tx + 16 * j] = acc[i][j];
        }
        __syncthreads();  // ps visible, everyone done with K in kvs

        // Load V tile into the same buffer.
        #pragma unroll
        for (int c = 0; c < (BK * D) / (NTH * 4); ++c) {
            int li  = c * NTH * 4 + tid * 4;
            int r   = li >> 7;
            int col = li & (D - 1);
            float4 val = *reinterpret_cast<const float4*>(v + (kt * BK + r) * D + col);
            *reinterpret_cast<float4*>(kvs + r * KSTR + col) = val;
        }
        __syncthreads();

        // O += P @ V: thread owns rows 4*ty+i, cols {tx*4..+3} and {64+tx*4..+3}.
        for (int j = 0; j < BK; ++j) {
            float4 v0 = *reinterpret_cast<const float4*>(kvs + j * KSTR + tx * 4);
            float4 v1 = *reinterpret_cast<const float4*>(kvs + j * KSTR + 64 + tx * 4);
            #pragma unroll
            for (int i = 0; i < 4; ++i) {
                float p = ps[(4 * ty + i) * PSTR + j];  // broadcast within ty group
                o[i][0] += p * v0.x;
                o[i][1] += p * v0.y;
                o[i][2] += p * v0.z;
                o[i][3] += p * v0.w;
                o[i][4] += p * v1.x;
                o[i][5] += p * v1.y;
                o[i][6] += p * v1.z;
                o[i][7] += p * v1.w;
            }
        }
    }

    // Epilogue: normalize and store.
    #pragma unroll
    for (int i = 0; i < 4; ++i) {
        float inv = 1.f / l[i];
        int row = row0 + 4 * ty + i;
        float* op = out + (b * LSEQ + row) * D;
        float4 r0 = make_float4(o[i][0] * inv, o[i][1] * inv, o[i][2] * inv, o[i][3] * inv);
        float4 r1 = make_float4(o[i][4] * inv, o[i][5] * inv, o[i][6] * inv, o[i][7] * inv);
        *reinterpret_cast<float4*>(op + tx * 4)      = r0;
        *reinterpret_cast<float4*>(op + 64 + tx * 4) = r1;
    }
}

// ---------------------------------------------------------------------------
extern "C" void kernel_launch(void* const* d_in, const int* in_sizes, int n_in,
                              void* d_out, int out_size)
{
    const float* x1 = (const float*)d_in[0];
    const float* x2 = (const float*)d_in[1];
    const float* x3 = (const float*)d_in[2];
    const float* Wq = (const float*)d_in[3];
    const float* bq = (const float*)d_in[4];
    const float* Wk = (const float*)d_in[5];
    const float* bk = (const float*)d_in[6];
    const float* Wv = (const float*)d_in[7];
    const float* bv = (const float*)d_in[8];
    float* out = (float*)d_out;

    const int proj_smem = (BQ * KSTR + D * KSTR) * (int)sizeof(float);              // ~101 KB
    const int attn_smem = (BQ * KSTR + BK * KSTR + BQ * PSTR) * (int)sizeof(float); // ~82 KB

    // One-time host-side attribute setup (host static: no device state, idempotent).
    static bool configured = false;
    if (!configured) {
        cudaFuncSetAttribute(proj_kernel, cudaFuncAttributeMaxDynamicSharedMemorySize, proj_smem);
        cudaFuncSetAttribute(attn_kernel, cudaFuncAttributeMaxDynamicSharedMemorySize, attn_smem);
        configured = true;
    }

    dim3 gproj((NB * LSEQ) / BQ, 1, 3);  // 256 row-tiles x 3 projections
    proj_kernel<<<gproj, NTH, proj_smem>>>(x1, x2, x3, Wq, bq, Wk, bk, Wv, bv);

    dim3 gattn(LSEQ / BQ, NB, 1);        // 64 q-tiles x 4 batches
    attn_kernel<<<gattn, NTH, attn_smem>>>(out);
}

// round 7
// speedup vs baseline: 3.4084x; 3.4084x over previous
#include <cuda_runtime.h>
#include <cuda_bf16.h>
#include <cstdint>

#define D     128
#define LSEQ  4096
#define NB    4

// ===========================================================================
// Base-ISA PTX helpers (sm_80-class: mma.sync / ldmatrix / cp.async only)
// ===========================================================================
__device__ __forceinline__ uint32_t smem_u32(const void* p) {
    uint32_t a;
    asm("{ .reg .u64 t; cvta.to.shared.u64 t, %1; cvt.u32.u64 %0, t; }" : "=r"(a) : "l"(p));
    return a;
}
__device__ __forceinline__ void mma_bf16(float* c, const uint32_t* a, uint32_t b0, uint32_t b1) {
    asm volatile("mma.sync.aligned.m16n8k16.row.col.f32.bf16.bf16.f32 "
        "{%0,%1,%2,%3}, {%4,%5,%6,%7}, {%8,%9}, {%0,%1,%2,%3};"
        : "+f"(c[0]), "+f"(c[1]), "+f"(c[2]), "+f"(c[3])
        : "r"(a[0]), "r"(a[1]), "r"(a[2]), "r"(a[3]), "r"(b0), "r"(b1));
}
__device__ __forceinline__ void ldsm4(uint32_t* r, uint32_t addr) {
    asm volatile("ldmatrix.sync.aligned.m8n8.x4.shared.b16 {%0,%1,%2,%3}, [%4];"
        : "=r"(r[0]), "=r"(r[1]), "=r"(r[2]), "=r"(r[3]) : "r"(addr));
}
__device__ __forceinline__ void ldsm4t(uint32_t* r, uint32_t addr) {
    asm volatile("ldmatrix.sync.aligned.m8n8.x4.trans.shared.b16 {%0,%1,%2,%3}, [%4];"
        : "=r"(r[0]), "=r"(r[1]), "=r"(r[2]), "=r"(r[3]) : "r"(addr));
}
__device__ __forceinline__ void cp16(uint32_t dst, const void* src) {
    asm volatile("cp.async.cg.shared.global [%0], [%1], 16;" :: "r"(dst), "l"(src));
}
#define CP_COMMIT() asm volatile("cp.async.commit_group;" ::: "memory")
#define CP_WAIT0()  asm volatile("cp.async.wait_group 0;" ::: "memory")
#define CP_WAIT1()  asm volatile("cp.async.wait_group 1;" ::: "memory")

__device__ __forceinline__ float ex2f(float x) {
    float y; asm("ex2.approx.ftz.f32 %0, %1;" : "=f"(y) : "f"(x)); return y;
}

// ===========================================================================
// Scratch: pre-split bf16 Q/K/V (hi + lo), row-major [NB*LSEQ][D]
// ===========================================================================
#define NEL (NB * LSEQ * D)
__device__ __align__(256) __nv_bfloat16 g_qhi[NEL];
__device__ __align__(256) __nv_bfloat16 g_qlo[NEL];
__device__ __align__(256) __nv_bfloat16 g_khi[NEL];
__device__ __align__(256) __nv_bfloat16 g_klo[NEL];
__device__ __align__(256) __nv_bfloat16 g_vhi[NEL];
__device__ __align__(256) __nv_bfloat16 g_vlo[NEL];

// ===========================================================================
// Projection kernel: y = x @ W^T + b, output split to bf16 hi/lo.
// Q additionally scaled by log2(e)/sqrt(D) so scores are in exp2 domain.
// ===========================================================================
#define PJ_BQ   64
#define PJ_NTH  256
#define PJ_KSTR 132

__global__ __launch_bounds__(PJ_NTH) void proj_kernel(
    const float* __restrict__ x1, const float* __restrict__ x2, const float* __restrict__ x3,
    const float* __restrict__ Wq, const float* __restrict__ bq,
    const float* __restrict__ Wk, const float* __restrict__ bk,
    const float* __restrict__ Wv, const float* __restrict__ bv)
{
    extern __shared__ float sm[];
    float* xs = sm;
    float* ws = sm + PJ_BQ * PJ_KSTR;

    const int z = blockIdx.z;
    const float* x    = (z == 0) ? x1 : (z == 1) ? x2 : x3;
    const float* W    = (z == 0) ? Wq : (z == 1) ? Wk : Wv;
    const float* bias = (z == 0) ? bq : (z == 1) ? bk : bv;
    __nv_bfloat16* yhi = (z == 0) ? g_qhi : (z == 1) ? g_khi : g_vhi;
    __nv_bfloat16* ylo = (z == 0) ? g_qlo : (z == 1) ? g_klo : g_vlo;
    const float oscale = (z == 0) ? (1.4426950408889634f * 0.08838834764831845f) : 1.0f;

    const int row0 = blockIdx.x * PJ_BQ;
    const int tid  = threadIdx.x;

    #pragma unroll
    for (int c = 0; c < (PJ_BQ * D) / (PJ_NTH * 4); ++c) {
        int li = c * PJ_NTH * 4 + tid * 4;
        int r = li >> 7, col = li & (D - 1);
        float4 val = *reinterpret_cast<const float4*>(x + (size_t)(row0 + r) * D + col);
        *reinterpret_cast<float4*>(xs + r * PJ_KSTR + col) = val;
    }
    #pragma unroll
    for (int c = 0; c < (D * D) / (PJ_NTH * 4); ++c) {
        int li = c * PJ_NTH * 4 + tid * 4;
        int r = li >> 7, col = li & (D - 1);
        float4 val = *reinterpret_cast<const float4*>(W + li);
        *reinterpret_cast<float4*>(ws + r * PJ_KSTR + col) = val;
    }
    __syncthreads();

    const int tx = tid & 15, ty = tid >> 4;
    float acc[4][8];
    #pragma unroll
    for (int i = 0; i < 4; ++i)
        #pragma unroll
        for (int j = 0; j < 8; ++j) acc[i][j] = 0.f;

    for (int d = 0; d < D; d += 4) {
        float4 xv[4];
        #pragma unroll
        for (int i = 0; i < 4; ++i)
            xv[i] = *reinterpret_cast<const float4*>(xs + (4 * ty + i) * PJ_KSTR + d);
        #pragma unroll
        for (int j = 0; j < 8; ++j) {
            float4 wv = *reinterpret_cast<const float4*>(ws + (tx + 16 * j) * PJ_KSTR + d);
            #pragma unroll
            for (int i = 0; i < 4; ++i) {
                acc[i][j] += xv[i].x * wv.x;
                acc[i][j] += xv[i].y * wv.y;
                acc[i][j] += xv[i].z * wv.z;
                acc[i][j] += xv[i].w * wv.w;
            }
        }
    }
    #pragma unroll
    for (int j = 0; j < 8; ++j) {
        const int e = tx + 16 * j;
        const float be = bias[e];
        #pragma unroll
        for (int i = 0; i < 4; ++i) {
            float val = (acc[i][j] + be) * oscale;
            __nv_bfloat16 h = __float2bfloat16_rn(val);
            __nv_bfloat16 l = __float2bfloat16_rn(val - __bfloat162float(h));
            size_t idx = (size_t)(row0 + 4 * ty + i) * D + e;
            yhi[idx] = h;
            ylo[idx] = l;
        }
    }
}

// ===========================================================================
// Flash attention via mma.sync bf16 (hi/lo 3-pass), no-max softmax.
// CTA: 128 Q rows, 8 warps (m16 each). BK=64. Double-buffered cp.async.
// ===========================================================================
#define BQ   128
#define BK   64
#define NKT  (LSEQ / BK)
#define AT_NTH 256

#define ROWB   272                       // 136 bf16 per row (128 data + pad)
#define TILE_B (64 * ROWB)               // one 64x128 bf16 tile = 17408 B
#define SMEM_ATTN (8 * TILE_B)           // 2 stages x 4 tiles = 139264 B
// stage tile ids: 0=Khi 1=Klo 2=Vhi 3=Vlo ; Q staging reuses stage 0's 4 tiles

__global__ __launch_bounds__(AT_NTH, 1) void attn_mma_kernel(float* __restrict__ out)
{
    extern __shared__ char smc[];
    const uint32_t sb = smem_u32(smc);

    const int tid = threadIdx.x;
    const int wid = tid >> 5;
    const int lid = tid & 31;

    const int b    = blockIdx.y;
    const int row0 = blockIdx.x * BQ;
    const size_t base = (size_t)b * LSEQ * D;
    const __nv_bfloat16* qh = g_qhi + base;
    const __nv_bfloat16* ql = g_qlo + base;
    const __nv_bfloat16* kh = g_khi + base;
    const __nv_bfloat16* kl = g_klo + base;
    const __nv_bfloat16* vh = g_vhi + base;
    const __nv_bfloat16* vl = g_vlo + base;

    // ---- stage Q (128 rows, hi+lo) into stage-0 buffers via cp.async ----
    #pragma unroll
    for (int i = 0; i < 8; ++i) {
        int chunk = tid + 256 * i;               // 0..2047
        int r = chunk >> 4, c = chunk & 15;
        int tq = r >> 6, rr = r & 63;
        const void* sh = qh + (size_t)(row0 + r) * D + c * 8;
        const void* sl = ql + (size_t)(row0 + r) * D + c * 8;
        cp16(sb + (uint32_t)(tq * TILE_B + rr * ROWB + c * 16), sh);
        cp16(sb + (uint32_t)((2 + tq) * TILE_B + rr * ROWB + c * 16), sl);
    }
    CP_COMMIT();
    CP_WAIT0();
    __syncthreads();

    // ---- Q fragments -> registers (m16k16 x 8 ksteps, hi+lo) ----
    uint32_t aqh[8][4], aql[8][4];
    {
        int grow = 16 * wid + (lid & 15);
        int th = grow >> 6, rIn = grow & 63;
        uint32_t colb = (uint32_t)(((lid >> 4) & 1) * 16);
        uint32_t bh = sb + (uint32_t)(th * TILE_B + rIn * ROWB) + colb;
        uint32_t bl = sb + (uint32_t)((2 + th) * TILE_B + rIn * ROWB) + colb;
        #pragma unroll
        for (int ks = 0; ks < 8; ++ks) {
            ldsm4(aqh[ks], bh + ks * 32);
            ldsm4(aql[ks], bl + ks * 32);
        }
    }
    __syncthreads();   // Q consumed; stage 0 free for K/V

    // lane-derived smem offsets for B fragments
    const uint32_t offK = (uint32_t)(((lid & 7) + 8 * ((lid >> 4) & 1)) * ROWB + ((lid >> 3) & 1) * 16);
    const uint32_t offV = (uint32_t)((lid & 15) * ROWB + ((lid >> 4) & 1) * 16);

    float oacc[16][4];
    #pragma unroll
    for (int t = 0; t < 16; ++t)
        #pragma unroll
        for (int r = 0; r < 4; ++r) oacc[t][r] = 0.f;
    float l0 = 0.f, l1 = 0.f;

    // prologue load: kt=0 into stage 0
    {
        const __nv_bfloat16* srcs[4] = {kh, kl, vh, vl};
        #pragma unroll
        for (int t = 0; t < 4; ++t)
            #pragma unroll
            for (int i = 0; i < 4; ++i) {
                int chunk = tid + 256 * i;
                int r = chunk >> 4, c = chunk & 15;
                cp16(sb + (uint32_t)(t * TILE_B + r * ROWB + c * 16),
                     srcs[t] + (size_t)r * D + c * 8);
            }
        CP_COMMIT();
    }

    for (int kt = 0; kt < NKT; ++kt) {
        const int s = kt & 1;
        // issue next stage
        if (kt < NKT - 1) {
            const __nv_bfloat16* srcs[4] = {kh, kl, vh, vl};
            const int sn = (kt + 1) & 1;
            #pragma unroll
            for (int t = 0; t < 4; ++t)
                #pragma unroll
                for (int i = 0; i < 4; ++i) {
                    int chunk = tid + 256 * i;
                    int r = chunk >> 4, c = chunk & 15;
                    cp16(sb + (uint32_t)((sn * 4 + t) * TILE_B + r * ROWB + c * 16),
                         srcs[t] + (size_t)((kt + 1) * BK + r) * D + c * 8);
                }
            CP_COMMIT();
            CP_WAIT1();
        } else {
            CP_WAIT0();
        }
        __syncthreads();

        const uint32_t bKhi = sb + (uint32_t)((s * 4 + 0) * TILE_B) + offK;
        const uint32_t bKlo = sb + (uint32_t)((s * 4 + 1) * TILE_B) + offK;
        const uint32_t bVhi = sb + (uint32_t)((s * 4 + 2) * TILE_B) + offV;
        const uint32_t bVlo = sb + (uint32_t)((s * 4 + 3) * TILE_B) + offV;

        // ---- S = Q K^T (3-pass split), fp32 accum: 8 n8-tiles of BK=64 ----
        float sacc[8][4];
        #pragma unroll
        for (int t = 0; t < 8; ++t)
            #pragma unroll
            for (int r = 0; r < 4; ++r) sacc[t][r] = 0.f;

        #pragma unroll
        for (int ks = 0; ks < 8; ++ks) {
            #pragma unroll
            for (int np = 0; np < 4; ++np) {
                uint32_t fkh[4], fkl[4];
                ldsm4(fkh, bKhi + (uint32_t)(np * 16 * ROWB + ks * 32));
                ldsm4(fkl, bKlo + (uint32_t)(np * 16 * ROWB + ks * 32));
                mma_bf16(sacc[2 * np],     aqh[ks], fkh[0], fkh[1]);
                mma_bf16(sacc[2 * np + 1], aqh[ks], fkh[2], fkh[3]);
                mma_bf16(sacc[2 * np],     aqh[ks], fkl[0], fkl[1]);
                mma_bf16(sacc[2 * np + 1], aqh[ks], fkl[2], fkl[3]);
                mma_bf16(sacc[2 * np],     aql[ks], fkh[0], fkh[1]);
                mma_bf16(sacc[2 * np + 1], aql[ks], fkh[2], fkh[3]);
            }
        }

        // ---- softmax (no max) + P hi/lo fragment build ----
        uint32_t ph[4][4], pl[4][4];
        #pragma unroll
        for (int kp = 0; kp < 4; ++kp) {
            #pragma unroll
            for (int half = 0; half < 2; ++half) {
                float* sc = sacc[2 * kp + half];
                float p0 = ex2f(sc[0]), p1 = ex2f(sc[1]);
                float p2 = ex2f(sc[2]), p3 = ex2f(sc[3]);
                l0 += p0 + p1;
                l1 += p2 + p3;
                __nv_bfloat162 h01 = __floats2bfloat162_rn(p0, p1);
                __nv_bfloat162 h23 = __floats2bfloat162_rn(p2, p3);
                float2 f01 = __bfloat1622float2(h01);
                float2 f23 = __bfloat1622float2(h23);
                __nv_bfloat162 r01 = __floats2bfloat162_rn(p0 - f01.x, p1 - f01.y);
                __nv_bfloat162 r23 = __floats2bfloat162_rn(p2 - f23.x, p3 - f23.y);
                ph[kp][2 * half + 0] = *reinterpret_cast<uint32_t*>(&h01);
                ph[kp][2 * half + 1] = *reinterpret_cast<uint32_t*>(&h23);
                pl[kp][2 * half + 0] = *reinterpret_cast<uint32_t*>(&r01);
                pl[kp][2 * half + 1] = *reinterpret_cast<uint32_t*>(&r23);
            }
        }

        // ---- O += P V (3-pass split): 16 d-tiles, 4 kv16 steps ----
        #pragma unroll
        for (int kp = 0; kp < 4; ++kp) {
            #pragma unroll
            for (int np = 0; np < 8; ++np) {
                uint32_t fvh[4], fvl[4];
                ldsm4t(fvh, bVhi + (uint32_t)(kp * 16 * ROWB + np * 32));
                ldsm4t(fvl, bVlo + (uint32_t)(kp * 16 * ROWB + np * 32));
                mma_bf16(oacc[2 * np],     ph[kp], fvh[0], fvh[1]);
                mma_bf16(oacc[2 * np + 1], ph[kp], fvh[2], fvh[3]);
                mma_bf16(oacc[2 * np],     ph[kp], fvl[0], fvl[1]);
                mma_bf16(oacc[2 * np + 1], ph[kp], fvl[2], fvl[3]);
                mma_bf16(oacc[2 * np],     pl[kp], fvh[0], fvh[1]);
                mma_bf16(oacc[2 * np + 1], pl[kp], fvh[2], fvh[3]);
            }
        }
        __syncthreads();   // all warps done with stage s before it is refilled
    }

    // ---- epilogue: reduce l over the 4 lanes sharing each row, store O/l ----
    l0 += __shfl_xor_sync(0xffffffffu, l0, 1);
    l0 += __shfl_xor_sync(0xffffffffu, l0, 2);
    l1 += __shfl_xor_sync(0xffffffffu, l1, 1);
    l1 += __shfl_xor_sync(0xffffffffu, l1, 2);
    const float inv0 = 1.f / l0;
    const float inv1 = 1.f / l1;

    const int r = lid >> 2, cg = lid & 3;
    const size_t row = (size_t)b * LSEQ + row0 + 16 * wid + r;
    #pragma unroll
    for (int t = 0; t < 16; ++t) {
        int col = 8 * t + 2 * cg;
        float2 v0 = make_float2(oacc[t][0] * inv0, oacc[t][1] * inv0);
        float2 v1 = make_float2(oacc[t][2] * inv1, oacc[t][3] * inv1);
        *reinterpret_cast<float2*>(out + row * D + col)       = v0;
        *reinterpret_cast<float2*>(out + (row + 8) * D + col) = v1;
    }
}

// ===========================================================================
extern "C" void kernel_launch(void* const* d_in, const int* in_sizes, int n_in,
                              void* d_out, int out_size)
{
    const float* x1 = (const float*)d_in[0];
    const float* x2 = (const float*)d_in[1];
    const float* x3 = (const float*)d_in[2];
    const float* Wq = (const float*)d_in[3];
    const float* bq = (const float*)d_in[4];
    const float* Wk = (const float*)d_in[5];
    const float* bk = (const float*)d_in[6];
    const float* Wv = (const float*)d_in[7];
    const float* bv = (const float*)d_in[8];
    float* out = (float*)d_out;

    const int proj_smem = (PJ_BQ * PJ_KSTR + D * PJ_KSTR) * (int)sizeof(float);

    static bool configured = false;
    if (!configured) {
        cudaFuncSetAttribute(proj_kernel, cudaFuncAttributeMaxDynamicSharedMemorySize, proj_smem);
        cudaFuncSetAttribute(attn_mma_kernel, cudaFuncAttributeMaxDynamicSharedMemorySize, SMEM_ATTN);
        configured = true;
    }

    dim3 gproj((NB * LSEQ) / PJ_BQ, 1, 3);
    proj_kernel<<<gproj, PJ_NTH, proj_smem>>>(x1, x2, x3, Wq, bq, Wk, bk, Wv, bv);

    dim3 gattn(LSEQ / BQ, NB, 1);   // 32 x 4 = 128 CTAs, 1 wave
    attn_mma_kernel<<<gattn, AT_NTH, SMEM_ATTN>>>(out);
}

// round 12
// speedup vs baseline: 3.8777x; 1.1377x over previous
#include <cuda_runtime.h>
#include <cuda_bf16.h>
#include <cuda_fp16.h>
#include <cstdint>

#define D     128
#define LSEQ  4096
#define NB    4

// ===========================================================================
// Base-ISA PTX helpers (sm_80-class: mma.sync / ldmatrix / cp.async only)
// ===========================================================================
__device__ __forceinline__ uint32_t smem_u32(const void* p) {
    uint32_t a;
    asm("{ .reg .u64 t; cvta.to.shared.u64 t, %1; cvt.u32.u64 %0, t; }" : "=r"(a) : "l"(p));
    return a;
}
// volatile: pins the hand-scheduled pass-major order (R7-proven compile path).
__device__ __forceinline__ void mma_bf16(float* c, const uint32_t* a, uint32_t b0, uint32_t b1) {
    asm volatile("mma.sync.aligned.m16n8k16.row.col.f32.bf16.bf16.f32 "
        "{%0,%1,%2,%3}, {%4,%5,%6,%7}, {%8,%9}, {%0,%1,%2,%3};"
        : "+f"(c[0]), "+f"(c[1]), "+f"(c[2]), "+f"(c[3])
        : "r"(a[0]), "r"(a[1]), "r"(a[2]), "r"(a[3]), "r"(b0), "r"(b1));
}
__device__ __forceinline__ void mma_f16(float* c, const uint32_t* a, uint32_t b0, uint32_t b1) {
    asm volatile("mma.sync.aligned.m16n8k16.row.col.f32.f16.f16.f32 "
        "{%0,%1,%2,%3}, {%4,%5,%6,%7}, {%8,%9}, {%0,%1,%2,%3};"
        : "+f"(c[0]), "+f"(c[1]), "+f"(c[2]), "+f"(c[3])
        : "r"(a[0]), "r"(a[1]), "r"(a[2]), "r"(a[3]), "r"(b0), "r"(b1));
}
__device__ __forceinline__ void ldsm4(uint32_t* r, uint32_t addr) {
    asm volatile("ldmatrix.sync.aligned.m8n8.x4.shared.b16 {%0,%1,%2,%3}, [%4];"
        : "=r"(r[0]), "=r"(r[1]), "=r"(r[2]), "=r"(r[3]) : "r"(addr));
}
__device__ __forceinline__ void ldsm4t(uint32_t* r, uint32_t addr) {
    asm volatile("ldmatrix.sync.aligned.m8n8.x4.trans.shared.b16 {%0,%1,%2,%3}, [%4];"
        : "=r"(r[0]), "=r"(r[1]), "=r"(r[2]), "=r"(r[3]) : "r"(addr));
}
__device__ __forceinline__ void cp16(uint32_t dst, const void* src) {
    asm volatile("cp.async.cg.shared.global [%0], [%1], 16;" :: "r"(dst), "l"(src));
}
#define CP_COMMIT() asm volatile("cp.async.commit_group;" ::: "memory")
#define CP_WAIT0()  asm volatile("cp.async.wait_group 0;" ::: "memory")
#define CP_WAIT1()  asm volatile("cp.async.wait_group 1;" ::: "memory")

__device__ __forceinline__ float ex2f(float x) {
    float y; asm("ex2.approx.ftz.f32 %0, %1;" : "=f"(y) : "f"(x)); return y;
}

// ===========================================================================
// Scratch: pre-split Q/K (bf16 hi/lo) and V (fp16 hi/lo), row-major
// ===========================================================================
#define NEL (NB * LSEQ * D)
__device__ __align__(256) __nv_bfloat16 g_qhi[NEL];
__device__ __align__(256) __nv_bfloat16 g_qlo[NEL];
__device__ __align__(256) __nv_bfloat16 g_khi[NEL];
__device__ __align__(256) __nv_bfloat16 g_klo[NEL];
__device__ __align__(256) __half        g_vhi[NEL];
__device__ __align__(256) __half        g_vlo[NEL];

// ===========================================================================
// Projection kernel: y = x @ W^T + b, split outputs. Q scaled by log2e/sqrt(D).
// Epilogue stages hi/lo in smem for coalesced uint4 global stores.
// ===========================================================================
#define PJ_BQ   64
#define PJ_NTH  256
#define PJ_KSTR 132
#define PJ_OSTR 136   // halfwords per staged row

__global__ __launch_bounds__(PJ_NTH) void proj_kernel(
    const float* __restrict__ x1, const float* __restrict__ x2, const float* __restrict__ x3,
    const float* __restrict__ Wq, const float* __restrict__ bq,
    const float* __restrict__ Wk, const float* __restrict__ bk,
    const float* __restrict__ Wv, const float* __restrict__ bv)
{
    extern __shared__ float sm[];
    float* xs = sm;
    float* ws = sm + PJ_BQ * PJ_KSTR;

    const int z = blockIdx.z;
    const float* x    = (z == 0) ? x1 : (z == 1) ? x2 : x3;
    const float* W    = (z == 0) ? Wq : (z == 1) ? Wk : Wv;
    const float* bias = (z == 0) ? bq : (z == 1) ? bk : bv;
    uint16_t* yhi = (z == 0) ? (uint16_t*)g_qhi : (z == 1) ? (uint16_t*)g_khi : (uint16_t*)g_vhi;
    uint16_t* ylo = (z == 0) ? (uint16_t*)g_qlo : (z == 1) ? (uint16_t*)g_klo : (uint16_t*)g_vlo;
    const float oscale = (z == 0) ? (1.4426950408889634f * 0.08838834764831845f) : 1.0f;
    const bool  isV    = (z == 2);

    const int row0 = blockIdx.x * PJ_BQ;
    const int tid  = threadIdx.x;

    #pragma unroll
    for (int c = 0; c < (PJ_BQ * D) / (PJ_NTH * 4); ++c) {
        int li = c * PJ_NTH * 4 + tid * 4;
        int r = li >> 7, col = li & (D - 1);
        float4 val = *reinterpret_cast<const float4*>(x + (size_t)(row0 + r) * D + col);
        *reinterpret_cast<float4*>(xs + r * PJ_KSTR + col) = val;
    }
    #pragma unroll
    for (int c = 0; c < (D * D) / (PJ_NTH * 4); ++c) {
        int li = c * PJ_NTH * 4 + tid * 4;
        int r = li >> 7, col = li & (D - 1);
        float4 val = *reinterpret_cast<const float4*>(W + li);
        *reinterpret_cast<float4*>(ws + r * PJ_KSTR + col) = val;
    }
    __syncthreads();

    const int tx = tid & 15, ty = tid >> 4;
    float acc[4][8];
    #pragma unroll
    for (int i = 0; i < 4; ++i)
        #pragma unroll
        for (int j = 0; j < 8; ++j) acc[i][j] = 0.f;

    for (int d = 0; d < D; d += 4) {
        float4 xv[4];
        #pragma unroll
        for (int i = 0; i < 4; ++i)
            xv[i] = *reinterpret_cast<const float4*>(xs + (4 * ty + i) * PJ_KSTR + d);
        #pragma unroll
        for (int j = 0; j < 8; ++j) {
            float4 wv = *reinterpret_cast<const float4*>(ws + (tx + 16 * j) * PJ_KSTR + d);
            #pragma unroll
            for (int i = 0; i < 4; ++i) {
                acc[i][j] += xv[i].x * wv.x;
                acc[i][j] += xv[i].y * wv.y;
                acc[i][j] += xv[i].z * wv.z;
                acc[i][j] += xv[i].w * wv.w;
            }
        }
    }

    // bias + scale + split, staged to smem (reuses xs/ws space)
    float be[8];
    #pragma unroll
    for (int j = 0; j < 8; ++j) be[j] = bias[tx + 16 * j];
    __syncthreads();

    uint16_t* hb = reinterpret_cast<uint16_t*>(sm);        // [64][PJ_OSTR]
    uint16_t* lb = hb + PJ_BQ * PJ_OSTR;
    #pragma unroll
    for (int j = 0; j < 8; ++j) {
        const int e = tx + 16 * j;
        #pragma unroll
        for (int i = 0; i < 4; ++i) {
            float val = (acc[i][j] + be[j]) * oscale;
            uint16_t h, l;
            if (isV) {
                __half hh = __float2half_rn(val);
                __half ll = __float2half_rn(val - __half2float(hh));
                h = *reinterpret_cast<uint16_t*>(&hh);
                l = *reinterpret_cast<uint16_t*>(&ll);
            } else {
                __nv_bfloat16 hh = __float2bfloat16_rn(val);
                __nv_bfloat16 ll = __float2bfloat16_rn(val - __bfloat162float(hh));
                h = *reinterpret_cast<uint16_t*>(&hh);
                l = *reinterpret_cast<uint16_t*>(&ll);
            }
            hb[(4 * ty + i) * PJ_OSTR + e] = h;
            lb[(4 * ty + i) * PJ_OSTR + e] = l;
        }
    }
    __syncthreads();

    // coalesced stores: 1024 uint4 per buffer
    #pragma unroll
    for (int c = 0; c < 4; ++c) {
        int idx = tid + 256 * c;          // 0..1023
        int r = idx >> 4, c8 = idx & 15;  // 16 uint4 per row
        uint4 hv = *reinterpret_cast<const uint4*>(hb + r * PJ_OSTR + c8 * 8);
        uint4 lv = *reinterpret_cast<const uint4*>(lb + r * PJ_OSTR + c8 * 8);
        *reinterpret_cast<uint4*>(yhi + (size_t)(row0 + r) * D + c8 * 8) = hv;
        *reinterpret_cast<uint4*>(ylo + (size_t)(row0 + r) * D + c8 * 8) = lv;
    }
}

// ===========================================================================
// Flash attention: S = 3-pass bf16 split; PV = 2-pass fp16 (Phi*Vhi + Phi*Vlo).
// No-max softmax, fp32 O accumulators, double-buffered cp.async.
// ===========================================================================
#define BQ   128
#define BK   64
#define NKT  (LSEQ / BK)
#define AT_NTH 256

#define ROWB   272                       // 136 halfwords per row (128 data + pad)
#define TILE_B (64 * ROWB)               // one 64x128 16-bit tile = 17408 B
#define SMEM_ATTN (8 * TILE_B)           // 2 stages x 4 tiles = 139264 B
// stage tile ids: 0=Khi 1=Klo 2=Vhi 3=Vlo ; Q staging reuses stage 0's 4 tiles

__global__ __launch_bounds__(AT_NTH, 1) void attn_mma_kernel(float* __restrict__ out)
{
    extern __shared__ char smc[];
    const uint32_t sb = smem_u32(smc);

    const int tid = threadIdx.x;
    const int wid = tid >> 5;
    const int lid = tid & 31;

    const int b    = blockIdx.y;
    const int row0 = blockIdx.x * BQ;
    const size_t base = (size_t)b * LSEQ * D * 2;   // byte offset
    const char* qh = (const char*)g_qhi + base;
    const char* ql = (const char*)g_qlo + base;
    const char* kh = (const char*)g_khi + base;
    const char* kl = (const char*)g_klo + base;
    const char* vh = (const char*)g_vhi + base;
    const char* vl = (const char*)g_vlo + base;

    // ---- stage Q (128 rows, hi+lo) into stage-0 buffers via cp.async ----
    #pragma unroll
    for (int i = 0; i < 8; ++i) {
        int chunk = tid + 256 * i;               // 0..2047
        int r = chunk >> 4, c = chunk & 15;
        int tq = r >> 6, rr = r & 63;
        cp16(sb + (uint32_t)(tq * TILE_B + rr * ROWB + c * 16),
             qh + (size_t)(row0 + r) * 256 + c * 16);
        cp16(sb + (uint32_t)((2 + tq) * TILE_B + rr * ROWB + c * 16),
             ql + (size_t)(row0 + r) * 256 + c * 16);
    }
    CP_COMMIT();
    CP_WAIT0();
    __syncthreads();

    // ---- Q fragments -> registers (m16k16 x 8 ksteps, hi+lo) ----
    uint32_t aqh[8][4], aql[8][4];
    {
        int grow = 16 * wid + (lid & 15);
        int th = grow >> 6, rIn = grow & 63;
        uint32_t colb = (uint32_t)(((lid >> 4) & 1) * 16);
        uint32_t bh = sb + (uint32_t)(th * TILE_B + rIn * ROWB) + colb;
        uint32_t bl = sb + (uint32_t)((2 + th) * TILE_B + rIn * ROWB) + colb;
        #pragma unroll
        for (int ks = 0; ks < 8; ++ks) {
            ldsm4(aqh[ks], bh + ks * 32);
            ldsm4(aql[ks], bl + ks * 32);
        }
    }
    __syncthreads();   // Q consumed; stage 0 free for K/V

    const uint32_t offK = (uint32_t)(((lid & 7) + 8 * ((lid >> 4) & 1)) * ROWB + ((lid >> 3) & 1) * 16);
    const uint32_t offV = (uint32_t)((lid & 15) * ROWB + ((lid >> 4) & 1) * 16);

    float oacc[16][4];
    #pragma unroll
    for (int t = 0; t < 16; ++t)
        #pragma unroll
        for (int r = 0; r < 4; ++r) oacc[t][r] = 0.f;
    float l0 = 0.f, l1 = 0.f;

    // prologue load: kt=0 into stage 0
    {
        const char* srcs[4] = {kh, kl, vh, vl};
        #pragma unroll
        for (int t = 0; t < 4; ++t)
            #pragma unroll
            for (int i = 0; i < 4; ++i) {
                int chunk = tid + 256 * i;
                int r = chunk >> 4, c = chunk & 15;
                cp16(sb + (uint32_t)(t * TILE_B + r * ROWB + c * 16),
                     srcs[t] + (size_t)r * 256 + c * 16);
            }
        CP_COMMIT();
    }

    for (int kt = 0; kt < NKT; ++kt) {
        const int s = kt & 1;
        if (kt < NKT - 1) {
            const char* srcs[4] = {kh, kl, vh, vl};
            const int sn = (kt + 1) & 1;
            #pragma unroll
            for (int t = 0; t < 4; ++t)
                #pragma unroll
                for (int i = 0; i < 4; ++i) {
                    int chunk = tid + 256 * i;
                    int r = chunk >> 4, c = chunk & 15;
                    cp16(sb + (uint32_t)((sn * 4 + t) * TILE_B + r * ROWB + c * 16),
                         srcs[t] + (size_t)((kt + 1) * BK + r) * 256 + c * 16);
                }
            CP_COMMIT();
            CP_WAIT1();
        } else {
            CP_WAIT0();
        }
        __syncthreads();

        const uint32_t bKhi = sb + (uint32_t)((s * 4 + 0) * TILE_B) + offK;
        const uint32_t bKlo = sb + (uint32_t)((s * 4 + 1) * TILE_B) + offK;
        const uint32_t bVhi = sb + (uint32_t)((s * 4 + 2) * TILE_B) + offV;
        const uint32_t bVlo = sb + (uint32_t)((s * 4 + 3) * TILE_B) + offV;

        // ---- S = Q K^T, 3-pass bf16 split, pass-major (chain spacing 8) ----
        float sacc[8][4];
        #pragma unroll
        for (int t = 0; t < 8; ++t)
            #pragma unroll
            for (int r = 0; r < 4; ++r) sacc[t][r] = 0.f;

        #pragma unroll
        for (int ks = 0; ks < 8; ++ks) {
            uint32_t fkh[4][4], fkl[4][4];
            #pragma unroll
            for (int np = 0; np < 4; ++np) {
                ldsm4(fkh[np], bKhi + (uint32_t)(np * 16 * ROWB + ks * 32));
                ldsm4(fkl[np], bKlo + (uint32_t)(np * 16 * ROWB + ks * 32));
            }
            #pragma unroll
            for (int np = 0; np < 4; ++np) {
                mma_bf16(sacc[2 * np],     aqh[ks], fkh[np][0], fkh[np][1]);
                mma_bf16(sacc[2 * np + 1], aqh[ks], fkh[np][2], fkh[np][3]);
            }
            #pragma unroll
            for (int np = 0; np < 4; ++np) {
                mma_bf16(sacc[2 * np],     aqh[ks], fkl[np][0], fkl[np][1]);
                mma_bf16(sacc[2 * np + 1], aqh[ks], fkl[np][2], fkl[np][3]);
            }
            #pragma unroll
            for (int np = 0; np < 4; ++np) {
                mma_bf16(sacc[2 * np],     aql[ks], fkh[np][0], fkh[np][1]);
                mma_bf16(sacc[2 * np + 1], aql[ks], fkh[np][2], fkh[np][3]);
            }
        }

        // ---- softmax (no max): P hi fragments only, fp16 ----
        uint32_t ph[4][4];
        #pragma unroll
        for (int kp = 0; kp < 4; ++kp) {
            #pragma unroll
            for (int half = 0; half < 2; ++half) {
                float* sc = sacc[2 * kp + half];
                float p0 = ex2f(sc[0]), p1 = ex2f(sc[1]);
                float p2 = ex2f(sc[2]), p3 = ex2f(sc[3]);
                l0 += p0 + p1;
                l1 += p2 + p3;
                __half2 h01 = __floats2half2_rn(p0, p1);
                __half2 h23 = __floats2half2_rn(p2, p3);
                ph[kp][2 * half + 0] = *reinterpret_cast<uint32_t*>(&h01);
                ph[kp][2 * half + 1] = *reinterpret_cast<uint32_t*>(&h23);
            }
        }

        // ---- O += P V, 2-pass fp16 (Phi*Vhi + Phi*Vlo), np-pairs (spacing 4) ----
        #pragma unroll
        for (int kp = 0; kp < 4; ++kp) {
            #pragma unroll
            for (int npp = 0; npp < 4; ++npp) {
                const int np0 = 2 * npp, np1 = 2 * npp + 1;
                uint32_t fha[4], fla[4], fhb[4], flb[4];
                ldsm4t(fha, bVhi + (uint32_t)(kp * 16 * ROWB + np0 * 32));
                ldsm4t(fla, bVlo + (uint32_t)(kp * 16 * ROWB + np0 * 32));
                ldsm4t(fhb, bVhi + (uint32_t)(kp * 16 * ROWB + np1 * 32));
                ldsm4t(flb, bVlo + (uint32_t)(kp * 16 * ROWB + np1 * 32));
                mma_f16(oacc[2 * np0],     ph[kp], fha[0], fha[1]);
                mma_f16(oacc[2 * np0 + 1], ph[kp], fha[2], fha[3]);
                mma_f16(oacc[2 * np1],     ph[kp], fhb[0], fhb[1]);
                mma_f16(oacc[2 * np1 + 1], ph[kp], fhb[2], fhb[3]);
                mma_f16(oacc[2 * np0],     ph[kp], fla[0], fla[1]);
                mma_f16(oacc[2 * np0 + 1], ph[kp], fla[2], fla[3]);
                mma_f16(oacc[2 * np1],     ph[kp], flb[0], flb[1]);
                mma_f16(oacc[2 * np1 + 1], ph[kp], flb[2], flb[3]);
            }
        }
        __syncthreads();   // all warps done with stage s before refill
    }

    // ---- epilogue: reduce l across quad lanes, normalize, store ----
    l0 += __shfl_xor_sync(0xffffffffu, l0, 1);
    l0 += __shfl_xor_sync(0xffffffffu, l0, 2);
    l1 += __shfl_xor_sync(0xffffffffu, l1, 1);
    l1 += __shfl_xor_sync(0xffffffffu, l1, 2);
    const float inv0 = 1.f / l0;
    const float inv1 = 1.f / l1;

    const int r = lid >> 2, cg = lid & 3;
    const size_t row = (size_t)b * LSEQ + row0 + 16 * wid + r;
    #pragma unroll
    for (int t = 0; t < 16; ++t) {
        int col = 8 * t + 2 * cg;
        float2 v0 = make_float2(oacc[t][0] * inv0, oacc[t][1] * inv0);
        float2 v1 = make_float2(oacc[t][2] * inv1, oacc[t][3] * inv1);
        *reinterpret_cast<float2*>(out + row * D + col)       = v0;
        *reinterpret_cast<float2*>(out + (row + 8) * D + col) = v1;
    }
}

// ===========================================================================
extern "C" void kernel_launch(void* const* d_in, const int* in_sizes, int n_in,
                              void* d_out, int out_size)
{
    const float* x1 = (const float*)d_in[0];
    const float* x2 = (const float*)d_in[1];
    const float* x3 = (const float*)d_in[2];
    const float* Wq = (const float*)d_in[3];
    const float* bq = (const float*)d_in[4];
    const float* Wk = (const float*)d_in[5];
    const float* bk = (const float*)d_in[6];
    const float* Wv = (const float*)d_in[7];
    const float* bv = (const float*)d_in[8];
    float* out = (float*)d_out;

    const int proj_smem = (PJ_BQ * PJ_KSTR + D * PJ_KSTR) * (int)sizeof(float);

    static bool configured = false;
    if (!configured) {
        cudaFuncSetAttribute(proj_kernel, cudaFuncAttributeMaxDynamicSharedMemorySize, proj_smem);
        cudaFuncSetAttribute(attn_mma_kernel, cudaFuncAttributeMaxDynamicSharedMemorySize, SMEM_ATTN);
        configured = true;
    }

    dim3 gproj((NB * LSEQ) / PJ_BQ, 1, 3);
    proj_kernel<<<gproj, PJ_NTH, proj_smem>>>(x1, x2, x3, Wq, bq, Wk, bk, Wv, bv);

    dim3 gattn(LSEQ / BQ, NB, 1);   // 128 CTAs, 1 wave
    attn_mma_kernel<<<gattn, AT_NTH, SMEM_ATTN>>>(out);
}

// round 13
// speedup vs baseline: 5.9210x; 1.5269x over previous
#include <cuda_runtime.h>
#include <cuda_bf16.h>
#include <cuda_fp16.h>
#include <cstdint>

#define D     128
#define LSEQ  4096
#define NB    4

// ===========================================================================
// Base-ISA PTX helpers (sm_80-class: mma.sync / ldmatrix / cp.async only)
// ===========================================================================
__device__ __forceinline__ uint32_t smem_u32(const void* p) {
    uint32_t a;
    asm("{ .reg .u64 t; cvta.to.shared.u64 t, %1; cvt.u32.u64 %0, t; }" : "=r"(a) : "l"(p));
    return a;
}
// volatile: pins the hand-scheduled pass-major order (R7/R12-proven compile path).
__device__ __forceinline__ void mma_f16(float* c, const uint32_t* a, uint32_t b0, uint32_t b1) {
    asm volatile("mma.sync.aligned.m16n8k16.row.col.f32.f16.f16.f32 "
        "{%0,%1,%2,%3}, {%4,%5,%6,%7}, {%8,%9}, {%0,%1,%2,%3};"
        : "+f"(c[0]), "+f"(c[1]), "+f"(c[2]), "+f"(c[3])
        : "r"(a[0]), "r"(a[1]), "r"(a[2]), "r"(a[3]), "r"(b0), "r"(b1));
}
__device__ __forceinline__ void ldsm4(uint32_t* r, uint32_t addr) {
    asm volatile("ldmatrix.sync.aligned.m8n8.x4.shared.b16 {%0,%1,%2,%3}, [%4];"
        : "=r"(r[0]), "=r"(r[1]), "=r"(r[2]), "=r"(r[3]) : "r"(addr));
}
__device__ __forceinline__ void ldsm4t(uint32_t* r, uint32_t addr) {
    asm volatile("ldmatrix.sync.aligned.m8n8.x4.trans.shared.b16 {%0,%1,%2,%3}, [%4];"
        : "=r"(r[0]), "=r"(r[1]), "=r"(r[2]), "=r"(r[3]) : "r"(addr));
}
__device__ __forceinline__ void cp16(uint32_t dst, const void* src) {
    asm volatile("cp.async.cg.shared.global [%0], [%1], 16;" :: "r"(dst), "l"(src));
}
#define CP_COMMIT() asm volatile("cp.async.commit_group;" ::: "memory")
#define CP_WAIT0()  asm volatile("cp.async.wait_group 0;" ::: "memory")
#define CP_WAIT1()  asm volatile("cp.async.wait_group 1;" ::: "memory")

__device__ __forceinline__ float ex2f(float x) {
    float y; asm("ex2.approx.ftz.f32 %0, %1;" : "=f"(y) : "f"(x)); return y;
}

// ===========================================================================
// Scratch: Q fp16 hi/lo (precision guard on the exp-amplified path),
// K and V single fp16. Row-major [NB*LSEQ][D].
// ===========================================================================
#define NEL (NB * LSEQ * D)
__device__ __align__(256) __half g_qhi[NEL];
__device__ __align__(256) __half g_qlo[NEL];
__device__ __align__(256) __half g_k16[NEL];
__device__ __align__(256) __half g_v16[NEL];

// ===========================================================================
// Projection kernel: y = x @ W^T + b. Q scaled by log2e/sqrt(D), split hi/lo;
// K and V rounded to single fp16. Smem-staged coalesced uint4 stores.
// ===========================================================================
#define PJ_BQ   64
#define PJ_NTH  256
#define PJ_KSTR 132
#define PJ_OSTR 136   // halfwords per staged row

__global__ __launch_bounds__(PJ_NTH) void proj_kernel(
    const float* __restrict__ x1, const float* __restrict__ x2, const float* __restrict__ x3,
    const float* __restrict__ Wq, const float* __restrict__ bq,
    const float* __restrict__ Wk, const float* __restrict__ bk,
    const float* __restrict__ Wv, const float* __restrict__ bv)
{
    extern __shared__ float sm[];
    float* xs = sm;
    float* ws = sm + PJ_BQ * PJ_KSTR;

    const int z = blockIdx.z;
    const float* x    = (z == 0) ? x1 : (z == 1) ? x2 : x3;
    const float* W    = (z == 0) ? Wq : (z == 1) ? Wk : Wv;
    const float* bias = (z == 0) ? bq : (z == 1) ? bk : bv;
    uint16_t* yhi = (z == 0) ? (uint16_t*)g_qhi : (z == 1) ? (uint16_t*)g_k16 : (uint16_t*)g_v16;
    const float oscale = (z == 0) ? (1.4426950408889634f * 0.08838834764831845f) : 1.0f;
    const bool  hasLo  = (z == 0);

    const int row0 = blockIdx.x * PJ_BQ;
    const int tid  = threadIdx.x;

    #pragma unroll
    for (int c = 0; c < (PJ_BQ * D) / (PJ_NTH * 4); ++c) {
        int li = c * PJ_NTH * 4 + tid * 4;
        int r = li >> 7, col = li & (D - 1);
        float4 val = *reinterpret_cast<const float4*>(x + (size_t)(row0 + r) * D + col);
        *reinterpret_cast<float4*>(xs + r * PJ_KSTR + col) = val;
    }
    #pragma unroll
    for (int c = 0; c < (D * D) / (PJ_NTH * 4); ++c) {
        int li = c * PJ_NTH * 4 + tid * 4;
        int r = li >> 7, col = li & (D - 1);
        float4 val = *reinterpret_cast<const float4*>(W + li);
        *reinterpret_cast<float4*>(ws + r * PJ_KSTR + col) = val;
    }
    __syncthreads();

    const int tx = tid & 15, ty = tid >> 4;
    float acc[4][8];
    #pragma unroll
    for (int i = 0; i < 4; ++i)
        #pragma unroll
        for (int j = 0; j < 8; ++j) acc[i][j] = 0.f;

    for (int d = 0; d < D; d += 4) {
        float4 xv[4];
        #pragma unroll
        for (int i = 0; i < 4; ++i)
            xv[i] = *reinterpret_cast<const float4*>(xs + (4 * ty + i) * PJ_KSTR + d);
        #pragma unroll
        for (int j = 0; j < 8; ++j) {
            float4 wv = *reinterpret_cast<const float4*>(ws + (tx + 16 * j) * PJ_KSTR + d);
            #pragma unroll
            for (int i = 0; i < 4; ++i) {
                acc[i][j] += xv[i].x * wv.x;
                acc[i][j] += xv[i].y * wv.y;
                acc[i][j] += xv[i].z * wv.z;
                acc[i][j] += xv[i].w * wv.w;
            }
        }
    }

    float be[8];
    #pragma unroll
    for (int j = 0; j < 8; ++j) be[j] = bias[tx + 16 * j];
    __syncthreads();

    uint16_t* hb = reinterpret_cast<uint16_t*>(sm);        // [64][PJ_OSTR]
    uint16_t* lb = hb + PJ_BQ * PJ_OSTR;
    #pragma unroll
    for (int j = 0; j < 8; ++j) {
        const int e = tx + 16 * j;
        #pragma unroll
        for (int i = 0; i < 4; ++i) {
            float val = (acc[i][j] + be[j]) * oscale;
            __half hh = __float2half_rn(val);
            hb[(4 * ty + i) * PJ_OSTR + e] = *reinterpret_cast<uint16_t*>(&hh);
            if (hasLo) {
                __half ll = __float2half_rn(val - __half2float(hh));
                lb[(4 * ty + i) * PJ_OSTR + e] = *reinterpret_cast<uint16_t*>(&ll);
            }
        }
    }
    __syncthreads();

    #pragma unroll
    for (int c = 0; c < 4; ++c) {
        int idx = tid + 256 * c;          // 0..1023
        int r = idx >> 4, c8 = idx & 15;  // 16 uint4 per row
        uint4 hv = *reinterpret_cast<const uint4*>(hb + r * PJ_OSTR + c8 * 8);
        *reinterpret_cast<uint4*>(yhi + (size_t)(row0 + r) * D + c8 * 8) = hv;
        if (hasLo) {
            uint4 lv = *reinterpret_cast<const uint4*>(lb + r * PJ_OSTR + c8 * 8);
            *reinterpret_cast<uint4*>((uint16_t*)g_qlo + (size_t)(row0 + r) * D + c8 * 8) = lv;
        }
    }
}

// ===========================================================================
// Flash attention, all fp16: S = Qhi*K + Qlo*K (2-pass); PV = P*V (1 pass).
// No-max softmax, fp32 accumulators, double-buffered cp.async.
// ===========================================================================
#define BQ   128
#define BK   64
#define NKT  (LSEQ / BK)
#define AT_NTH 256

#define ROWB   272                       // 136 halfwords per row (128 data + pad)
#define TILE_B (64 * ROWB)               // one 64x128 fp16 tile = 17408 B
#define SMEM_ATTN (4 * TILE_B)           // 2 stages x {K,V} = 69632 B
// stage s tiles: (2s+0)=K, (2s+1)=V. Q staging uses all 4 tiles transiently.

__global__ __launch_bounds__(AT_NTH, 1) void attn_mma_kernel(float* __restrict__ out)
{
    extern __shared__ char smc[];
    const uint32_t sb = smem_u32(smc);

    const int tid = threadIdx.x;
    const int wid = tid >> 5;
    const int lid = tid & 31;

    const int b    = blockIdx.y;
    const int row0 = blockIdx.x * BQ;
    const size_t base = (size_t)b * LSEQ * D * 2;   // byte offset
    const char* qh = (const char*)g_qhi + base;
    const char* ql = (const char*)g_qlo + base;
    const char* kg = (const char*)g_k16 + base;
    const char* vg = (const char*)g_v16 + base;

    // ---- stage Q (128 rows, hi+lo) across all 4 tiles via cp.async ----
    #pragma unroll
    for (int i = 0; i < 8; ++i) {
        int chunk = tid + 256 * i;               // 0..2047
        int r = chunk >> 4, c = chunk & 15;
        int tq = r >> 6, rr = r & 63;
        cp16(sb + (uint32_t)(tq * TILE_B + rr * ROWB + c * 16),
             qh + (size_t)(row0 + r) * 256 + c * 16);
        cp16(sb + (uint32_t)((2 + tq) * TILE_B + rr * ROWB + c * 16),
             ql + (size_t)(row0 + r) * 256 + c * 16);
    }
    CP_COMMIT();
    CP_WAIT0();
    __syncthreads();

    // ---- Q fragments -> registers (m16k16 x 8 ksteps, hi+lo) ----
    uint32_t aqh[8][4], aql[8][4];
    {
        int grow = 16 * wid + (lid & 15);
        int th = grow >> 6, rIn = grow & 63;
        uint32_t colb = (uint32_t)(((lid >> 4) & 1) * 16);
        uint32_t bh = sb + (uint32_t)(th * TILE_B + rIn * ROWB) + colb;
        uint32_t bl = sb + (uint32_t)((2 + th) * TILE_B + rIn * ROWB) + colb;
        #pragma unroll
        for (int ks = 0; ks < 8; ++ks) {
            ldsm4(aqh[ks], bh + ks * 32);
            ldsm4(aql[ks], bl + ks * 32);
        }
    }
    __syncthreads();   // Q consumed; tiles free for K/V pipeline

    const uint32_t offK = (uint32_t)(((lid & 7) + 8 * ((lid >> 4) & 1)) * ROWB + ((lid >> 3) & 1) * 16);
    const uint32_t offV = (uint32_t)((lid & 15) * ROWB + ((lid >> 4) & 1) * 16);

    float oacc[16][4];
    #pragma unroll
    for (int t = 0; t < 16; ++t)
        #pragma unroll
        for (int r = 0; r < 4; ++r) oacc[t][r] = 0.f;
    float l0 = 0.f, l1 = 0.f;

    // prologue: kt=0 into stage 0 (tiles 0,1)
    {
        const char* srcs[2] = {kg, vg};
        #pragma unroll
        for (int t = 0; t < 2; ++t)
            #pragma unroll
            for (int i = 0; i < 4; ++i) {
                int chunk = tid + 256 * i;       // 0..1023
                int r = chunk >> 4, c = chunk & 15;
                cp16(sb + (uint32_t)(t * TILE_B + r * ROWB + c * 16),
                     srcs[t] + (size_t)r * 256 + c * 16);
            }
        CP_COMMIT();
    }

    for (int kt = 0; kt < NKT; ++kt) {
        const int s = kt & 1;
        if (kt < NKT - 1) {
            const char* srcs[2] = {kg, vg};
            const int sn = (kt + 1) & 1;
            #pragma unroll
            for (int t = 0; t < 2; ++t)
                #pragma unroll
                for (int i = 0; i < 4; ++i) {
                    int chunk = tid + 256 * i;
                    int r = chunk >> 4, c = chunk & 15;
                    cp16(sb + (uint32_t)((sn * 2 + t) * TILE_B + r * ROWB + c * 16),
                         srcs[t] + (size_t)((kt + 1) * BK + r) * 256 + c * 16);
                }
            CP_COMMIT();
            CP_WAIT1();
        } else {
            CP_WAIT0();
        }
        __syncthreads();

        const uint32_t bK = sb + (uint32_t)((s * 2 + 0) * TILE_B) + offK;
        const uint32_t bV = sb + (uint32_t)((s * 2 + 1) * TILE_B) + offV;

        // ---- S = Qhi*K + Qlo*K (2-pass), pass-major, chain spacing 8 ----
        float sacc[8][4];
        #pragma unroll
        for (int t = 0; t < 8; ++t)
            #pragma unroll
            for (int r = 0; r < 4; ++r) sacc[t][r] = 0.f;

        #pragma unroll
        for (int ks = 0; ks < 8; ++ks) {
            uint32_t fk[4][4];
            #pragma unroll
            for (int np = 0; np < 4; ++np)
                ldsm4(fk[np], bK + (uint32_t)(np * 16 * ROWB + ks * 32));
            #pragma unroll
            for (int np = 0; np < 4; ++np) {
                mma_f16(sacc[2 * np],     aqh[ks], fk[np][0], fk[np][1]);
                mma_f16(sacc[2 * np + 1], aqh[ks], fk[np][2], fk[np][3]);
            }
            #pragma unroll
            for (int np = 0; np < 4; ++np) {
                mma_f16(sacc[2 * np],     aql[ks], fk[np][0], fk[np][1]);
                mma_f16(sacc[2 * np + 1], aql[ks], fk[np][2], fk[np][3]);
            }
        }

        // ---- softmax (no max): P fp16 fragments ----
        uint32_t ph[4][4];
        #pragma unroll
        for (int kp = 0; kp < 4; ++kp) {
            #pragma unroll
            for (int half = 0; half < 2; ++half) {
                float* sc = sacc[2 * kp + half];
                float p0 = ex2f(sc[0]), p1 = ex2f(sc[1]);
                float p2 = ex2f(sc[2]), p3 = ex2f(sc[3]);
                l0 += p0 + p1;
                l1 += p2 + p3;
                __half2 h01 = __floats2half2_rn(p0, p1);
                __half2 h23 = __floats2half2_rn(p2, p3);
                ph[kp][2 * half + 0] = *reinterpret_cast<uint32_t*>(&h01);
                ph[kp][2 * half + 1] = *reinterpret_cast<uint32_t*>(&h23);
            }
        }

        // ---- O += P V (single pass), acc reuse distance 16 ----
        #pragma unroll
        for (int kp = 0; kp < 4; ++kp) {
            #pragma unroll
            for (int npp = 0; npp < 4; ++npp) {
                const int np0 = 2 * npp, np1 = 2 * npp + 1;
                uint32_t fva[4], fvb[4];
                ldsm4t(fva, bV + (uint32_t)(kp * 16 * ROWB + np0 * 32));
                ldsm4t(fvb, bV + (uint32_t)(kp * 16 * ROWB + np1 * 32));
                mma_f16(oacc[2 * np0],     ph[kp], fva[0], fva[1]);
                mma_f16(oacc[2 * np0 + 1], ph[kp], fva[2], fva[3]);
                mma_f16(oacc[2 * np1],     ph[kp], fvb[0], fvb[1]);
                mma_f16(oacc[2 * np1 + 1], ph[kp], fvb[2], fvb[3]);
            }
        }
        __syncthreads();   // all warps done with stage s before refill
    }

    // ---- epilogue: reduce l across quad lanes, normalize, store ----
    l0 += __shfl_xor_sync(0xffffffffu, l0, 1);
    l0 += __shfl_xor_sync(0xffffffffu, l0, 2);
    l1 += __shfl_xor_sync(0xffffffffu, l1, 1);
    l1 += __shfl_xor_sync(0xffffffffu, l1, 2);
    const float inv0 = 1.f / l0;
    const float inv1 = 1.f / l1;

    const int r = lid >> 2, cg = lid & 3;
    const size_t row = (size_t)b * LSEQ + row0 + 16 * wid + r;
    #pragma unroll
    for (int t = 0; t < 16; ++t) {
        int col = 8 * t + 2 * cg;
        float2 v0 = make_float2(oacc[t][0] * inv0, oacc[t][1] * inv0);
        float2 v1 = make_float2(oacc[t][2] * inv1, oacc[t][3] * inv1);
        *reinterpret_cast<float2*>(out + row * D + col)       = v0;
        *reinterpret_cast<float2*>(out + (row + 8) * D + col) = v1;
    }
}

// ===========================================================================
extern "C" void kernel_launch(void* const* d_in, const int* in_sizes, int n_in,
                              void* d_out, int out_size)
{
    const float* x1 = (const float*)d_in[0];
    const float* x2 = (const float*)d_in[1];
    const float* x3 = (const float*)d_in[2];
    const float* Wq = (const float*)d_in[3];
    const float* bq = (const float*)d_in[4];
    const float* Wk = (const float*)d_in[5];
    const float* bk = (const float*)d_in[6];
    const float* Wv = (const float*)d_in[7];
    const float* bv = (const float*)d_in[8];
    float* out = (float*)d_out;

    const int proj_smem = (PJ_BQ * PJ_KSTR + D * PJ_KSTR) * (int)sizeof(float);

    static bool configured = false;
    if (!configured) {
        cudaFuncSetAttribute(proj_kernel, cudaFuncAttributeMaxDynamicSharedMemorySize, proj_smem);
        cudaFuncSetAttribute(attn_mma_kernel, cudaFuncAttributeMaxDynamicSharedMemorySize, SMEM_ATTN);
        configured = true;
    }

    dim3 gproj((NB * LSEQ) / PJ_BQ, 1, 3);
    proj_kernel<<<gproj, PJ_NTH, proj_smem>>>(x1, x2, x3, Wq, bq, Wk, bk, Wv, bv);

    dim3 gattn(LSEQ / BQ, NB, 1);   // 128 CTAs, 1 wave
    attn_mma_kernel<<<gattn, AT_NTH, SMEM_ATTN>>>(out);
}